// round 9
// baseline (speedup 1.0000x reference)
#include <cuda_runtime.h>

// MSAColumnGlobalAttention: B=1, s=1024, i=512, c=8, h=8
// Kernel A (per-column CTA, 512 thr, 2 CTAs/SM, spill-free): LN -> store x
//   immediately (transient regs); xbar -> qk; logits recompute from g_x
//   (L1/L2 hot) -> raw e -> scratch; 0.5/sum -> g_rcp.
// Kernel B unchanged (at f32x2 pipe floor).

#define LN_EPS 1e-5f
#define I_DIM 512
#define S_DIM 1024
#define A_THREADS 512
#define NWARP (A_THREADS / 32)
#define B_THREADS 256

struct WeightsB {
    float Wv2[64];
    float Wg2[512];   // pairs over h, PRE-SCALED by 0.5
    float WoP[512];   // pairs over h / co
    float Bo[8];
};

__device__   WeightsB g_stage;
__constant__ WeightsB cw;
__device__   float g_x[S_DIM * I_DIM * 8];    // normalized x
__device__   float g_w[S_DIM * I_DIM * 8];    // RAW exp(logit)
__device__   float g_rcp[I_DIM * 8];          // 0.5 / sum_t e

// ---- f32x2 helpers ----
__device__ __forceinline__ float2 fma2(float2 a, float2 b, float2 c) {
    unsigned long long ra = *reinterpret_cast<unsigned long long*>(&a);
    unsigned long long rb = *reinterpret_cast<unsigned long long*>(&b);
    unsigned long long rc = *reinterpret_cast<unsigned long long*>(&c);
    unsigned long long rd;
    asm("fma.rn.f32x2 %0, %1, %2, %3;" : "=l"(rd) : "l"(ra), "l"(rb), "l"(rc));
    return *reinterpret_cast<float2*>(&rd);
}
__device__ __forceinline__ float2 mul2(float2 a, float2 b) {
    unsigned long long ra = *reinterpret_cast<unsigned long long*>(&a);
    unsigned long long rb = *reinterpret_cast<unsigned long long*>(&b);
    unsigned long long rd;
    asm("mul.rn.f32x2 %0, %1, %2;" : "=l"(rd) : "l"(ra), "l"(rb));
    return *reinterpret_cast<float2*>(&rd);
}
__device__ __forceinline__ float2 dup(float x) { return make_float2(x, x); }
__device__ __forceinline__ float2 lo2(float4 w) { return make_float2(w.x, w.y); }
__device__ __forceinline__ float2 hi2(float4 w) { return make_float2(w.z, w.w); }

__device__ __forceinline__ float tanh_apx(float x) {
    float y; asm("tanh.approx.f32 %0, %1;" : "=f"(y) : "f"(x)); return y;
}

#define PAIRDOT8(acc, xd, w0, w1, w2, w3)            \
    acc = mul2(xd[0], lo2(w0));                      \
    acc = fma2(xd[1], hi2(w0), acc);                 \
    acc = fma2(xd[2], lo2(w1), acc);                 \
    acc = fma2(xd[3], hi2(w1), acc);                 \
    acc = fma2(xd[4], lo2(w2), acc);                 \
    acc = fma2(xd[5], hi2(w2), acc);                 \
    acc = fma2(xd[6], lo2(w3), acc);                 \
    acc = fma2(xd[7], hi2(w3), acc);

// Transpose-reduce: lane l ends with warp total of channel (l & 7). 9 SHFLs.
__device__ __forceinline__ float wreduce8(const float v[8], int lane) {
    float a[4];
#pragma unroll
    for (int p = 0; p < 4; p++) {
        const float lo = v[2 * p], hi = v[2 * p + 1];
        const float send = (lane & 1) ? lo : hi;
        const float recv = __shfl_xor_sync(0xffffffffu, send, 1);
        a[p] = ((lane & 1) ? hi : lo) + recv;
    }
    float b[2];
#pragma unroll
    for (int p = 0; p < 2; p++) {
        const float lo = a[2 * p], hi = a[2 * p + 1];
        const float send = (lane & 2) ? lo : hi;
        const float recv = __shfl_xor_sync(0xffffffffu, send, 2);
        b[p] = ((lane & 2) ? hi : lo) + recv;
    }
    {
        const float lo = b[0], hi = b[1];
        const float send = (lane & 4) ? lo : hi;
        const float recv = __shfl_xor_sync(0xffffffffu, send, 4);
        float r = ((lane & 4) ? hi : lo) + recv;
        r += __shfl_xor_sync(0xffffffffu, r, 8);
        r += __shfl_xor_sync(0xffffffffu, r, 16);
        return r;
    }
}

// ============================ Kernel A ============================
__global__ __launch_bounds__(A_THREADS, 2)
void msa_attn_weights_kernel(const float* __restrict__ m,
                             const float* __restrict__ gamma,
                             const float* __restrict__ beta,
                             const float* __restrict__ wq,
                             const float* __restrict__ wk,
                             const float* __restrict__ wv,
                             const float* __restrict__ wg,
                             const float* __restrict__ wo,
                             const float* __restrict__ bo)
{
    const int i    = blockIdx.x;
    const int tid  = threadIdx.x;
    const int lane = tid & 31;
    const int warp = tid >> 5;

    __shared__ float sWq[512];
    __shared__ float sWk[64];
    __shared__ float sRed[NWARP][8];
    __shared__ float sXbar[8];
    __shared__ float sQK[64];

    sWq[tid] = wq[tid];
    if (tid < 64) sWk[tid] = wk[tid];

    // CTA 0 repacks streaming weights (overlapped with other CTAs' LN)
    if (i == 0) {
        const int row = tid >> 3, j = tid & 7;
        const int h = row >> 3, c = row & 7;
        g_stage.Wg2[((h >> 1) * 8 + c) * 16 + (j >> 1) * 4 + (j & 1) * 2 + (h & 1)] = 0.5f * wg[tid];
        const int co = tid >> 6, idx = tid & 63;
        const int hh = idx >> 3, cc = idx & 7;
        g_stage.WoP[(((hh >> 1) * 8 + cc) * 4 + (co >> 1)) * 4 + (co & 1) * 2 + (hh & 1)] = wo[tid];
        if (tid < 64) {
            const int c2 = tid >> 3, j2 = tid & 7;
            g_stage.Wv2[(c2 >> 1) * 16 + (j2 >> 1) * 4 + (j2 & 1) * 2 + (c2 & 1)] = wv[tid];
        }
        if (tid < 8) g_stage.Bo[tid] = bo[tid];
    }

    // ---- phase 1: LN both rows (transient), store x, accumulate column sum ----
    float acc[8];
#pragma unroll
    for (int c = 0; c < 8; c++) acc[c] = 0.f;
    {
        const float4 ga = __ldg(reinterpret_cast<const float4*>(gamma));
        const float4 gb = __ldg(reinterpret_cast<const float4*>(gamma + 4));
        const float4 ba = __ldg(reinterpret_cast<const float4*>(beta));
        const float4 bb = __ldg(reinterpret_cast<const float4*>(beta + 4));
        const float gam[8] = {ga.x, ga.y, ga.z, ga.w, gb.x, gb.y, gb.z, gb.w};
        const float bet[8] = {ba.x, ba.y, ba.z, ba.w, bb.x, bb.y, bb.z, bb.w};

#pragma unroll
        for (int r = 0; r < 2; r++) {
            const size_t gid = (size_t)(r * A_THREADS + tid) * I_DIM + i;
            const float4* p = reinterpret_cast<const float4*>(m + gid * 8);
            float4 a0 = p[0];
            float4 a1 = p[1];
            float xr[8] = {a0.x, a0.y, a0.z, a0.w, a1.x, a1.y, a1.z, a1.w};
            float mean = 0.f;
#pragma unroll
            for (int c = 0; c < 8; c++) mean += xr[c];
            mean *= 0.125f;
            float var = 0.f;
#pragma unroll
            for (int c = 0; c < 8; c++) { float d = xr[c] - mean; var = fmaf(d, d, var); }
            var *= 0.125f;
            const float rstd = rsqrtf(var + LN_EPS);
#pragma unroll
            for (int c = 0; c < 8; c++) {
                xr[c] = fmaf((xr[c] - mean) * rstd, gam[c], bet[c]);
                acc[c] += xr[c];
            }
            float4* px = reinterpret_cast<float4*>(&g_x[gid * 8]);
            px[0] = make_float4(xr[0], xr[1], xr[2], xr[3]);
            px[1] = make_float4(xr[4], xr[5], xr[6], xr[7]);
        }
    }

    {
        const float r = wreduce8(acc, lane);
        if (lane < 8) sRed[warp][lane] = r;
    }
    __syncthreads();
    if (tid < 8) {
        float s = sRed[0][tid];
#pragma unroll
        for (int w = 1; w < NWARP; w++) s += sRed[w][tid];
        sXbar[tid] = s;
    }
    __syncthreads();

    // qk[h][j] = sum_c (xbar . Wq[h*8+c]) * Wk[c][j], scaled
    if (tid < 64) {
        const int h = tid >> 3, j = tid & 7;
        float qk = 0.f;
#pragma unroll
        for (int c = 0; c < 8; c++) {
            float q = 0.f;
#pragma unroll
            for (int d = 0; d < 8; d++)
                q = fmaf(sXbar[d], sWq[(h * 8 + c) * 8 + d], q);
            qk = fmaf(q, sWk[c * 8 + j], qk);
        }
        const float qscale = (1.f / 1024.f) * 0.35355339059327373f;
        sQK[h * 8 + j] = qk * qscale;
    }
    __syncthreads();

    // ---- phase 2: reload x (L1/L2-hot), logits -> exp -> store raw e ----
    float hred[8];
#pragma unroll
    for (int h = 0; h < 8; h++) hred[h] = 0.f;

#pragma unroll
    for (int r = 0; r < 2; r++) {
        const size_t gid = (size_t)(r * A_THREADS + tid) * I_DIM + i;
        const float4* px = reinterpret_cast<const float4*>(&g_x[gid * 8]);
        const float4 xa = px[0], xb = px[1];
        const float x[8] = {xa.x, xa.y, xa.z, xa.w, xb.x, xb.y, xb.z, xb.w};

        float e[8];
#pragma unroll
        for (int h = 0; h < 8; h++) {
            const float4 qa = *reinterpret_cast<const float4*>(&sQK[h * 8]);
            const float4 qb = *reinterpret_cast<const float4*>(&sQK[h * 8 + 4]);
            float a = x[0] * qa.x, b = x[1] * qa.y;
            a = fmaf(x[2], qa.z, a);  b = fmaf(x[3], qa.w, b);
            a = fmaf(x[4], qb.x, a);  b = fmaf(x[5], qb.y, b);
            a = fmaf(x[6], qb.z, a);  b = fmaf(x[7], qb.w, b);
            e[h] = __expf(a + b);
            hred[h] += e[h];
        }
        float4* pw = reinterpret_cast<float4*>(&g_w[gid * 8]);
        pw[0] = make_float4(e[0], e[1], e[2], e[3]);
        pw[1] = make_float4(e[4], e[5], e[6], e[7]);
    }

    {
        const float r = wreduce8(hred, lane);
        if (lane < 8) sRed[warp][lane] = r;
    }
    __syncthreads();
    if (tid < 8) {
        float s = sRed[0][tid];
#pragma unroll
        for (int w = 1; w < NWARP; w++) s += sRed[w][tid];
        g_rcp[i * 8 + tid] = __fdividef(0.5f, s);
    }
}

// ============================ Kernel B ============================
__global__ __launch_bounds__(B_THREADS, 4)
void msa_stream_kernel(float* __restrict__ out)
{
    const size_t gid = (size_t)blockIdx.x * B_THREADS + threadIdx.x;  // = s*512 + i
    const int i = (int)(gid & (I_DIM - 1));

    float2 xd[8];
    {
        const float4* px = reinterpret_cast<const float4*>(&g_x[gid * 8]);
        const float4 xa = px[0], xb = px[1];
        xd[0] = dup(xa.x); xd[1] = dup(xa.y); xd[2] = dup(xa.z); xd[3] = dup(xa.w);
        xd[4] = dup(xb.x); xd[5] = dup(xb.y); xd[6] = dup(xb.z); xd[7] = dup(xb.w);
    }
    float2 whp[4];
    {
        const float4* pw = reinterpret_cast<const float4*>(&g_w[gid * 8]);
        const float4 wA = pw[0], wB = pw[1];
        const float4* pr = reinterpret_cast<const float4*>(&g_rcp[i * 8]);
        const float4 rA = __ldg(pr), rB = __ldg(pr + 1);
        whp[0] = mul2(lo2(wA), lo2(rA)); whp[1] = mul2(hi2(wA), hi2(rA));
        whp[2] = mul2(lo2(wB), lo2(rB)); whp[3] = mul2(hi2(wB), hi2(rB));
    }

    float2 v2[4];
#pragma unroll
    for (int cp = 0; cp < 4; cp++) {
        const float4* vp = reinterpret_cast<const float4*>(&cw.Wv2[cp * 16]);
        const float4 w0 = vp[0], w1 = vp[1], w2 = vp[2], w3 = vp[3];
        float2 a;
        PAIRDOT8(a, xd, w0, w1, w2, w3);
        v2[cp] = a;
    }

    float2 o2h[8];
#pragma unroll
    for (int co = 0; co < 8; co++) o2h[co] = make_float2(0.f, 0.f);

#pragma unroll
    for (int hp = 0; hp < 4; hp++) {
        const float2 wh = whp[hp];
#pragma unroll
        for (int c = 0; c < 8; c++) {
            const float4* gp = reinterpret_cast<const float4*>(&cw.Wg2[(hp * 8 + c) * 16]);
            const float4 ga = gp[0], gb = gp[1], gc = gp[2], gd = gp[3];
            float2 g2;
            PAIRDOT8(g2, xd, ga, gb, gc, gd);

            float2 t2 = make_float2(tanh_apx(g2.x), tanh_apx(g2.y));
            const float vc = (c & 1) ? v2[c >> 1].y : v2[c >> 1].x;
            const float2 hv = mul2(wh, dup(vc));
            const float2 coef = fma2(t2, hv, hv);

            const float4* op = reinterpret_cast<const float4*>(&cw.WoP[(hp * 8 + c) * 16]);
            const float4 u0 = op[0], u1 = op[1], u2 = op[2], u3 = op[3];
            o2h[0] = fma2(lo2(u0), coef, o2h[0]);
            o2h[1] = fma2(hi2(u0), coef, o2h[1]);
            o2h[2] = fma2(lo2(u1), coef, o2h[2]);
            o2h[3] = fma2(hi2(u1), coef, o2h[3]);
            o2h[4] = fma2(lo2(u2), coef, o2h[4]);
            o2h[5] = fma2(hi2(u2), coef, o2h[5]);
            o2h[6] = fma2(lo2(u3), coef, o2h[6]);
            o2h[7] = fma2(hi2(u3), coef, o2h[7]);
        }
    }

    float o[8];
#pragma unroll
    for (int co = 0; co < 8; co++) o[co] = (o2h[co].x + o2h[co].y) + cw.Bo[co];

    float4* po = reinterpret_cast<float4*>(out + gid * 8);
    po[0] = make_float4(o[0], o[1], o[2], o[3]);
    po[1] = make_float4(o[4], o[5], o[6], o[7]);
}

extern "C" void kernel_launch(void* const* d_in, const int* in_sizes, int n_in,
                              void* d_out, int out_size) {
    (void)in_sizes; (void)n_in; (void)out_size;
    const float* m  = (const float*)d_in[0];
    float* out      = (float*)d_out;

    msa_attn_weights_kernel<<<I_DIM, A_THREADS>>>(
        m,
        (const float*)d_in[1], (const float*)d_in[2], (const float*)d_in[3],
        (const float*)d_in[4], (const float*)d_in[5], (const float*)d_in[6],
        (const float*)d_in[7], (const float*)d_in[8]);

    void* pstage = nullptr;
    cudaGetSymbolAddress(&pstage, g_stage);
    cudaMemcpyToSymbolAsync(cw, pstage, sizeof(WeightsB), 0, cudaMemcpyDeviceToDevice, 0);

    msa_stream_kernel<<<(S_DIM * I_DIM) / B_THREADS, B_THREADS>>>(out);
}

// round 10
// speedup vs baseline: 1.2939x; 1.2939x over previous
#include <cuda_runtime.h>

// MSAColumnGlobalAttention: B=1, s=1024, i=512, c=8, h=8
// Kernel A (per-column CTA, 512 thr, x register-resident as in R8):
//   LN -> xbar -> qk -> logits -> RAW e -> g_w; 0.5/sum -> g_rcp.
//   No g_x scratch (A writes only 16MB + tables).
// Kernel B (streaming, 1 row/thr, 256x4): recomputes LN from m (bit-identical),
//   w = e * rcp; gate/sigmoid/Wo via f32x2 + constant weights.

#define LN_EPS 1e-5f
#define I_DIM 512
#define S_DIM 1024
#define A_THREADS 512
#define NWARP (A_THREADS / 32)
#define B_THREADS 256

struct WeightsB {
    float Wv2[64];
    float Wg2[512];   // pairs over h, PRE-SCALED by 0.5
    float WoP[512];   // pairs over h / co
    float Bo[8];
    float Gamma[8];
    float Beta[8];
};

__device__   WeightsB g_stage;
__constant__ WeightsB cw;
__device__   float g_w[S_DIM * I_DIM * 8];    // RAW exp(logit)
__device__   float g_rcp[I_DIM * 8];          // 0.5 / sum_t e

// ---- f32x2 helpers ----
__device__ __forceinline__ float2 fma2(float2 a, float2 b, float2 c) {
    unsigned long long ra = *reinterpret_cast<unsigned long long*>(&a);
    unsigned long long rb = *reinterpret_cast<unsigned long long*>(&b);
    unsigned long long rc = *reinterpret_cast<unsigned long long*>(&c);
    unsigned long long rd;
    asm("fma.rn.f32x2 %0, %1, %2, %3;" : "=l"(rd) : "l"(ra), "l"(rb), "l"(rc));
    return *reinterpret_cast<float2*>(&rd);
}
__device__ __forceinline__ float2 mul2(float2 a, float2 b) {
    unsigned long long ra = *reinterpret_cast<unsigned long long*>(&a);
    unsigned long long rb = *reinterpret_cast<unsigned long long*>(&b);
    unsigned long long rd;
    asm("mul.rn.f32x2 %0, %1, %2;" : "=l"(rd) : "l"(ra), "l"(rb));
    return *reinterpret_cast<float2*>(&rd);
}
__device__ __forceinline__ float2 dup(float x) { return make_float2(x, x); }
__device__ __forceinline__ float2 lo2(float4 w) { return make_float2(w.x, w.y); }
__device__ __forceinline__ float2 hi2(float4 w) { return make_float2(w.z, w.w); }

__device__ __forceinline__ float tanh_apx(float x) {
    float y; asm("tanh.approx.f32 %0, %1;" : "=f"(y) : "f"(x)); return y;
}

#define PAIRDOT8(acc, xd, w0, w1, w2, w3)            \
    acc = mul2(xd[0], lo2(w0));                      \
    acc = fma2(xd[1], hi2(w0), acc);                 \
    acc = fma2(xd[2], lo2(w1), acc);                 \
    acc = fma2(xd[3], hi2(w1), acc);                 \
    acc = fma2(xd[4], lo2(w2), acc);                 \
    acc = fma2(xd[5], hi2(w2), acc);                 \
    acc = fma2(xd[6], lo2(w3), acc);                 \
    acc = fma2(xd[7], hi2(w3), acc);

// Transpose-reduce: lane l ends with warp total of channel (l & 7). 9 SHFLs.
__device__ __forceinline__ float wreduce8(const float v[8], int lane) {
    float a[4];
#pragma unroll
    for (int p = 0; p < 4; p++) {
        const float lo = v[2 * p], hi = v[2 * p + 1];
        const float send = (lane & 1) ? lo : hi;
        const float recv = __shfl_xor_sync(0xffffffffu, send, 1);
        a[p] = ((lane & 1) ? hi : lo) + recv;
    }
    float b[2];
#pragma unroll
    for (int p = 0; p < 2; p++) {
        const float lo = a[2 * p], hi = a[2 * p + 1];
        const float send = (lane & 2) ? lo : hi;
        const float recv = __shfl_xor_sync(0xffffffffu, send, 2);
        b[p] = ((lane & 2) ? hi : lo) + recv;
    }
    {
        const float lo = b[0], hi = b[1];
        const float send = (lane & 4) ? lo : hi;
        const float recv = __shfl_xor_sync(0xffffffffu, send, 4);
        float r = ((lane & 4) ? hi : lo) + recv;
        r += __shfl_xor_sync(0xffffffffu, r, 8);
        r += __shfl_xor_sync(0xffffffffu, r, 16);
        return r;
    }
}

// ============================ Kernel A ============================
__global__ __launch_bounds__(A_THREADS, 2)
void msa_attn_weights_kernel(const float* __restrict__ m,
                             const float* __restrict__ gamma,
                             const float* __restrict__ beta,
                             const float* __restrict__ wq,
                             const float* __restrict__ wk,
                             const float* __restrict__ wv,
                             const float* __restrict__ wg,
                             const float* __restrict__ wo,
                             const float* __restrict__ bo)
{
    const int i    = blockIdx.x;
    const int tid  = threadIdx.x;
    const int lane = tid & 31;
    const int warp = tid >> 5;

    __shared__ float sWq[512];
    __shared__ float sWk[64];
    __shared__ float sRed[NWARP][8];
    __shared__ float sXbar[8];
    __shared__ float sQK[64];

    sWq[tid] = wq[tid];
    if (tid < 64) sWk[tid] = wk[tid];

    // CTA 0 repacks streaming weights (overlapped with other CTAs' LN)
    if (i == 0) {
        const int row = tid >> 3, j = tid & 7;
        const int h = row >> 3, c = row & 7;
        g_stage.Wg2[((h >> 1) * 8 + c) * 16 + (j >> 1) * 4 + (j & 1) * 2 + (h & 1)] = 0.5f * wg[tid];
        const int co = tid >> 6, idx = tid & 63;
        const int hh = idx >> 3, cc = idx & 7;
        g_stage.WoP[(((hh >> 1) * 8 + cc) * 4 + (co >> 1)) * 4 + (co & 1) * 2 + (hh & 1)] = wo[tid];
        if (tid < 64) {
            const int c2 = tid >> 3, j2 = tid & 7;
            g_stage.Wv2[(c2 >> 1) * 16 + (j2 >> 1) * 4 + (j2 & 1) * 2 + (c2 & 1)] = wv[tid];
        }
        if (tid < 8) {
            g_stage.Bo[tid]    = bo[tid];
            g_stage.Gamma[tid] = gamma[tid];
            g_stage.Beta[tid]  = beta[tid];
        }
    }

    float gam[8], bet[8];
    {
        const float4 ga = __ldg(reinterpret_cast<const float4*>(gamma));
        const float4 gb = __ldg(reinterpret_cast<const float4*>(gamma + 4));
        const float4 ba = __ldg(reinterpret_cast<const float4*>(beta));
        const float4 bb = __ldg(reinterpret_cast<const float4*>(beta + 4));
        gam[0]=ga.x; gam[1]=ga.y; gam[2]=ga.z; gam[3]=ga.w;
        gam[4]=gb.x; gam[5]=gb.y; gam[6]=gb.z; gam[7]=gb.w;
        bet[0]=ba.x; bet[1]=ba.y; bet[2]=ba.z; bet[3]=ba.w;
        bet[4]=bb.x; bet[5]=bb.y; bet[6]=bb.z; bet[7]=bb.w;
    }

    // ---- LN both rows (x stays in registers), accumulate column sum ----
    float x0[8], x1[8];
#pragma unroll
    for (int r = 0; r < 2; r++) {
        float* xr_out = r ? x1 : x0;
        const size_t gid = (size_t)(r * A_THREADS + tid) * I_DIM + i;
        const float4* p = reinterpret_cast<const float4*>(m + gid * 8);
        float4 a0 = p[0];
        float4 a1 = p[1];
        float xr[8] = {a0.x, a0.y, a0.z, a0.w, a1.x, a1.y, a1.z, a1.w};
        float mean = 0.f;
#pragma unroll
        for (int c = 0; c < 8; c++) mean += xr[c];
        mean *= 0.125f;
        float var = 0.f;
#pragma unroll
        for (int c = 0; c < 8; c++) { float d = xr[c] - mean; var = fmaf(d, d, var); }
        var *= 0.125f;
        const float rstd = rsqrtf(var + LN_EPS);
#pragma unroll
        for (int c = 0; c < 8; c++)
            xr_out[c] = fmaf((xr[c] - mean) * rstd, gam[c], bet[c]);
    }

    {
        float acc[8];
#pragma unroll
        for (int c = 0; c < 8; c++) acc[c] = x0[c] + x1[c];
        const float r = wreduce8(acc, lane);
        if (lane < 8) sRed[warp][lane] = r;
    }
    __syncthreads();
    if (tid < 8) {
        float s = sRed[0][tid];
#pragma unroll
        for (int w = 1; w < NWARP; w++) s += sRed[w][tid];
        sXbar[tid] = s;
    }
    __syncthreads();

    // qk[h][j] = sum_c (xbar . Wq[h*8+c]) * Wk[c][j], scaled
    if (tid < 64) {
        const int h = tid >> 3, j = tid & 7;
        float qk = 0.f;
#pragma unroll
        for (int c = 0; c < 8; c++) {
            float q = 0.f;
#pragma unroll
            for (int d = 0; d < 8; d++)
                q = fmaf(sXbar[d], sWq[(h * 8 + c) * 8 + d], q);
            qk = fmaf(q, sWk[c * 8 + j], qk);
        }
        const float qscale = (1.f / 1024.f) * 0.35355339059327373f;
        sQK[h * 8 + j] = qk * qscale;
    }
    __syncthreads();

    // logits -> exp (no max subtraction; logits bounded ~8), store RAW e
    float hred[8];
    {
        float e0[8], e1[8];
#pragma unroll
        for (int h = 0; h < 8; h++) {
            const float4 qa = *reinterpret_cast<const float4*>(&sQK[h * 8]);
            const float4 qb = *reinterpret_cast<const float4*>(&sQK[h * 8 + 4]);
            float a0 = x0[0] * qa.x, b0 = x0[1] * qa.y;
            float a1 = x1[0] * qa.x, b1 = x1[1] * qa.y;
            a0 = fmaf(x0[2], qa.z, a0);  b0 = fmaf(x0[3], qa.w, b0);
            a1 = fmaf(x1[2], qa.z, a1);  b1 = fmaf(x1[3], qa.w, b1);
            a0 = fmaf(x0[4], qb.x, a0);  b0 = fmaf(x0[5], qb.y, b0);
            a1 = fmaf(x1[4], qb.x, a1);  b1 = fmaf(x1[5], qb.y, b1);
            a0 = fmaf(x0[6], qb.z, a0);  b0 = fmaf(x0[7], qb.w, b0);
            a1 = fmaf(x1[6], qb.z, a1);  b1 = fmaf(x1[7], qb.w, b1);
            e0[h] = __expf(a0 + b0);
            e1[h] = __expf(a1 + b1);
            hred[h] = e0[h] + e1[h];
        }
        float4* pw0 = reinterpret_cast<float4*>(&g_w[((size_t)tid * I_DIM + i) * 8]);
        pw0[0] = make_float4(e0[0], e0[1], e0[2], e0[3]);
        pw0[1] = make_float4(e0[4], e0[5], e0[6], e0[7]);
        float4* pw1 = reinterpret_cast<float4*>(&g_w[((size_t)(tid + A_THREADS) * I_DIM + i) * 8]);
        pw1[0] = make_float4(e1[0], e1[1], e1[2], e1[3]);
        pw1[1] = make_float4(e1[4], e1[5], e1[6], e1[7]);
    }

    {
        const float r = wreduce8(hred, lane);
        if (lane < 8) sRed[warp][lane] = r;
    }
    __syncthreads();
    if (tid < 8) {
        float s = sRed[0][tid];
#pragma unroll
        for (int w = 1; w < NWARP; w++) s += sRed[w][tid];
        g_rcp[i * 8 + tid] = __fdividef(0.5f, s);
    }
}

// ============================ Kernel B ============================
__global__ __launch_bounds__(B_THREADS, 4)
void msa_stream_kernel(const float* __restrict__ m,
                       float* __restrict__ out)
{
    const size_t gid = (size_t)blockIdx.x * B_THREADS + threadIdx.x;  // = s*512 + i
    const int i = (int)(gid & (I_DIM - 1));

    // LN recompute (bit-identical to A's)
    float2 xd[8];
    {
        const float4* p = reinterpret_cast<const float4*>(m + gid * 8);
        float4 a0 = p[0];
        float4 a1 = p[1];
        float xr[8] = {a0.x, a0.y, a0.z, a0.w, a1.x, a1.y, a1.z, a1.w};
        float mean = 0.f;
#pragma unroll
        for (int c = 0; c < 8; c++) mean += xr[c];
        mean *= 0.125f;
        float var = 0.f;
#pragma unroll
        for (int c = 0; c < 8; c++) { float d = xr[c] - mean; var = fmaf(d, d, var); }
        var *= 0.125f;
        const float rstd = rsqrtf(var + LN_EPS);
#pragma unroll
        for (int c = 0; c < 8; c++)
            xd[c] = dup(fmaf((xr[c] - mean) * rstd, cw.Gamma[c], cw.Beta[c]));
    }

    float2 whp[4];
    {
        const float4* pw = reinterpret_cast<const float4*>(&g_w[gid * 8]);
        const float4 wA = pw[0], wB = pw[1];
        const float4* pr = reinterpret_cast<const float4*>(&g_rcp[i * 8]);
        const float4 rA = __ldg(pr), rB = __ldg(pr + 1);
        whp[0] = mul2(lo2(wA), lo2(rA)); whp[1] = mul2(hi2(wA), hi2(rA));
        whp[2] = mul2(lo2(wB), lo2(rB)); whp[3] = mul2(hi2(wB), hi2(rB));
    }

    float2 v2[4];
#pragma unroll
    for (int cp = 0; cp < 4; cp++) {
        const float4* vp = reinterpret_cast<const float4*>(&cw.Wv2[cp * 16]);
        const float4 w0 = vp[0], w1 = vp[1], w2 = vp[2], w3 = vp[3];
        float2 a;
        PAIRDOT8(a, xd, w0, w1, w2, w3);
        v2[cp] = a;
    }

    float2 o2h[8];
#pragma unroll
    for (int co = 0; co < 8; co++) o2h[co] = make_float2(0.f, 0.f);

#pragma unroll
    for (int hp = 0; hp < 4; hp++) {
        const float2 wh = whp[hp];
#pragma unroll
        for (int c = 0; c < 8; c++) {
            const float4* gp = reinterpret_cast<const float4*>(&cw.Wg2[(hp * 8 + c) * 16]);
            const float4 ga = gp[0], gb = gp[1], gc = gp[2], gd = gp[3];
            float2 g2;
            PAIRDOT8(g2, xd, ga, gb, gc, gd);

            float2 t2 = make_float2(tanh_apx(g2.x), tanh_apx(g2.y));
            const float vc = (c & 1) ? v2[c >> 1].y : v2[c >> 1].x;
            const float2 hv = mul2(wh, dup(vc));
            const float2 coef = fma2(t2, hv, hv);

            const float4* op = reinterpret_cast<const float4*>(&cw.WoP[(hp * 8 + c) * 16]);
            const float4 u0 = op[0], u1 = op[1], u2 = op[2], u3 = op[3];
            o2h[0] = fma2(lo2(u0), coef, o2h[0]);
            o2h[1] = fma2(hi2(u0), coef, o2h[1]);
            o2h[2] = fma2(lo2(u1), coef, o2h[2]);
            o2h[3] = fma2(hi2(u1), coef, o2h[3]);
            o2h[4] = fma2(lo2(u2), coef, o2h[4]);
            o2h[5] = fma2(hi2(u2), coef, o2h[5]);
            o2h[6] = fma2(lo2(u3), coef, o2h[6]);
            o2h[7] = fma2(hi2(u3), coef, o2h[7]);
        }
    }

    float o[8];
#pragma unroll
    for (int co = 0; co < 8; co++) o[co] = (o2h[co].x + o2h[co].y) + cw.Bo[co];

    float4* po = reinterpret_cast<float4*>(out + gid * 8);
    po[0] = make_float4(o[0], o[1], o[2], o[3]);
    po[1] = make_float4(o[4], o[5], o[6], o[7]);
}

extern "C" void kernel_launch(void* const* d_in, const int* in_sizes, int n_in,
                              void* d_out, int out_size) {
    (void)in_sizes; (void)n_in; (void)out_size;
    const float* m  = (const float*)d_in[0];
    float* out      = (float*)d_out;

    msa_attn_weights_kernel<<<I_DIM, A_THREADS>>>(
        m,
        (const float*)d_in[1], (const float*)d_in[2], (const float*)d_in[3],
        (const float*)d_in[4], (const float*)d_in[5], (const float*)d_in[6],
        (const float*)d_in[7], (const float*)d_in[8]);

    void* pstage = nullptr;
    cudaGetSymbolAddress(&pstage, g_stage);
    cudaMemcpyToSymbolAsync(cw, pstage, sizeof(WeightsB), 0, cudaMemcpyDeviceToDevice, 0);

    msa_stream_kernel<<<(S_DIM * I_DIM) / B_THREADS, B_THREADS>>>(m, out);
}